// round 7
// baseline (speedup 1.0000x reference)
#include <cuda_runtime.h>
#include <cstdint>

#define Hh 51
#define Lt 999
#define NB 16
#define NCTA 128
#define THREADS 256
#define WARPS 8
#define NTW 4          // max n8-tiles per warp; tiles with tau>=NTAU skipped
#define NTAU 26        // 26 tiles * 8 rows = 208 >= 204 real gate rows
#define NC1 7          // K-chunks layer1 (K=56: h1[51] + x + pad)
#define NC2 14         // K-chunks layer2 (K=112)
#define XCHP 65
#define RSTRIDE (2*NC1*128)   // per-region floats (hi+lo planes)

// shared memory float offsets
#define OFF_B1PK 0
#define SZ_B1PK (32*NC1*64)              // 14336
#define OFF_B2PK (OFF_B1PK + SZ_B1PK)
#define SZ_B2PK (32*NC2*64)              // 28672
#define OFF_HBUF (OFF_B2PK + SZ_B2PK)    // 4 regions x (hi,lo) x 7 chunks x 128
#define SZ_HBUF (4*RSTRIDE)              // 7168
#define OFF_XCH  (OFF_HBUF + SZ_HBUF)
#define OFF_OCH  (OFF_XCH + NB*XCHP)
#define OFF_OP   (OFF_OCH + NB*XCHP)     // 8 warps x 16
#define OFF_BLIN (OFF_OP + WARPS*NB)
#define SMEM_FLOATS (OFF_BLIN + 4)

__device__ __forceinline__ uint32_t to_tf32(float x) {
    uint32_t u; asm("cvt.rna.tf32.f32 %0, %1;" : "=r"(u) : "f"(x)); return u;
}
__device__ __forceinline__ void mma8(float* d, uint4 a, uint2 b) {
    asm("mma.sync.aligned.m16n8k8.row.col.f32.tf32.tf32.f32 "
        "{%0,%1,%2,%3}, {%4,%5,%6,%7}, {%8,%9}, {%0,%1,%2,%3};"
        : "+f"(d[0]), "+f"(d[1]), "+f"(d[2]), "+f"(d[3])
        : "r"(a.x), "r"(a.y), "r"(a.z), "r"(a.w), "r"(b.x), "r"(b.y));
}
__device__ __forceinline__ float frcp(float x) {
    float r; asm("rcp.approx.f32 %0, %1;" : "=f"(r) : "f"(x)); return r;
}
__device__ __forceinline__ float fex2(float x) {
    float r; asm("ex2.approx.f32 %0, %1;" : "=f"(r) : "f"(x)); return r;
}
__device__ __forceinline__ float sigf(float x) {
    return frcp(fex2(-1.4426950408889634f * x) + 1.0f);
}
__device__ __forceinline__ float ftanh(float x) {
    return fmaf(-2.0f, frcp(fex2(2.8853901817779268f * x) + 1.0f), 1.0f);
}
// hbuf slot for value (batch b, unit u), plane 0=hi 1=lo
__device__ __forceinline__ int hidx(int region, int plane, int b, int u) {
    const int colin = u & 7, ch = u >> 3;
    const int tl = ((b & 7) << 2) + (colin & 3);
    const int reg = ((colin >= 4) ? 2 : 0) + ((b >= 8) ? 1 : 0);
    return region*RSTRIDE + plane*(NC1*128) + ch*128 + tl*4 + reg;
}

__global__ void __launch_bounds__(THREADS, 1)
lstm_kernel(const float* __restrict__ x,
            const float* __restrict__ gWih1, const float* __restrict__ gWhh1,
            const float* __restrict__ gbih1, const float* __restrict__ gbhh1,
            const float* __restrict__ gWih2, const float* __restrict__ gWhh2,
            const float* __restrict__ gbih2, const float* __restrict__ gbhh2,
            const float* __restrict__ gWlin, const float* __restrict__ gblin,
            float* __restrict__ out)
{
    extern __shared__ float sm[];
    float* b1pk = sm + OFF_B1PK;
    float* b2pk = sm + OFF_B2PK;
    float* hbuf = sm + OFF_HBUF;
    uint32_t* hbu = (uint32_t*)hbuf;
    float* xch  = sm + OFF_XCH;
    float* och  = sm + OFF_OCH;
    float* opart= sm + OFF_OP;

    const int tid  = threadIdx.x;
    const int wid  = tid >> 5;
    const int lane = tid & 31;
    const int gid  = lane >> 2, tq = lane & 3;
    const int bmy  = gid + ((tq & 1) << 3);   // this lane's batch
    const int uh   = tq >> 1;                 // unit half within tile
    const int b0   = blockIdx.x * NB;

    // ---- pack layer-1 weights (tf32, fragment order); bias column ZERO ----
    for (int idx = tid; idx < SZ_B1PK; idx += THREADS) {
        const int r   = idx & 1;
        const int ln  = (idx >> 1) & 31;
        const int c   = (idx >> 6) % NC1;
        const int tau = idx / (NC1 * 64);
        const int n = tau*8 + (ln >> 2);
        const int u = n >> 2, ty = n & 3;
        const int k = c*8 + (ln & 3) + 4*r;
        float v = 0.f;
        if (u < Hh) {
            const int R = ty*Hh + u;
            if (k < Hh)       v = gWhh1[R*Hh + k];
            else if (k == Hh) v = gWih1[R];          // x slot (unit 51)
        }
        b1pk[idx] = __uint_as_float(to_tf32(v));
    }
    // ---- pack layer-2 weights; x and bias columns ZERO ----
    for (int idx = tid; idx < SZ_B2PK; idx += THREADS) {
        const int r   = idx & 1;
        const int ln  = (idx >> 1) & 31;
        const int c   = (idx >> 6) % NC2;
        const int tau = idx / (NC2 * 64);
        const int n = tau*8 + (ln >> 2);
        const int u = n >> 2, ty = n & 3;
        const int k = c*8 + (ln & 3) + 4*r;
        float v = 0.f;
        if (u < Hh) {
            const int R = ty*Hh + u;
            if (k < Hh) v = gWih2[R*Hh + k];
            else if (k >= 56) { const int kq = k - 56; if (kq < Hh) v = gWhh2[R*Hh + kq]; }
        }
        b2pk[idx] = __uint_as_float(to_tf32(v));
    }
    for (int i = tid; i < SZ_HBUF; i += THREADS) hbuf[i] = 0.f;
    if (tid == 0) sm[OFF_BLIN] = gblin[0];
    __syncthreads();
    // x_0 (region P0, both planes)
    if (tid < NB) {
        const float xv = x[(b0 + tid)*Lt + 0];
        const uint32_t hi = to_tf32(xv);
        hbu[hidx(0, 0, tid, 51)] = hi;
        hbu[hidx(0, 1, tid, 51)] = to_tf32(xv - __uint_as_float(hi));
    }
    // per-lane exact bias + W_lin
    float wl[NTW], bs1[NTW][4], bs2[NTW][4];
    #pragma unroll
    for (int j = 0; j < NTW; j++) {
        const int u = 2*(wid + 8*j) + uh;
        wl[j] = (u < Hh) ? gWlin[u] : 0.f;
        #pragma unroll
        for (int ty = 0; ty < 4; ty++) {
            const int R = ty*Hh + u;
            bs1[j][ty] = (u < Hh) ? (gbih1[R] + gbhh1[R]) : 0.f;
            bs2[j][ty] = (u < Hh) ? (gbih2[R] + gbhh2[R]) : 0.f;
        }
    }
    float cst1[NTW] = {0.f,0.f,0.f,0.f}, cst2[NTW] = {0.f,0.f,0.f,0.f};
    __syncthreads();

    int t0 = 0;
    for (int t = 0; t < Lt; ++t) {
        // ---- chunk boundary: stage x (coalesced) ----
        if ((t & 63) == 0) {
            t0 = t;
            int wd = Lt - t0; if (wd > 64) wd = 64;
            for (int i = tid; i < NB*64; i += THREADS) {
                const int row = i >> 6, col = i & 63;
                xch[row*XCHP + col] = (col < wd) ? x[(b0+row)*Lt + t0 + col] : 0.f;
            }
            __syncthreads();
            if (t0 > 0 && tid < NB) {
                const float xv = xch[tid*XCHP + 0];
                const uint32_t hi = to_tf32(xv);
                hbu[hidx(t0 & 1, 0, tid, 51)] = hi;
                hbu[hidx(t0 & 1, 1, tid, 51)] = to_tf32(xv - __uint_as_float(hi));
            }
            __syncthreads();
        }
        const int tloc = t - t0;
        const int pr = t & 1, pw = 1 - pr;       // P (h1) regions
        const int qr = 2 + pr, qw = 2 + pw;      // Q (h2) regions

        // ================= Layer 1 =================
        float acc[NTW][4];
        #pragma unroll
        for (int j = 0; j < NTW; j++) { acc[j][0]=acc[j][1]=acc[j][2]=acc[j][3]=0.f; }
        #pragma unroll
        for (int c = 0; c < NC1; c++) {
            const uint4 ah = *(const uint4*)&hbuf[pr*RSTRIDE + c*128 + lane*4];
            const uint4 al = *(const uint4*)&hbuf[pr*RSTRIDE + NC1*128 + c*128 + lane*4];
            #pragma unroll
            for (int j = 0; j < NTW; j++) {
                const int tau = wid + 8*j;
                if (tau < NTAU) {
                    const uint2 bv = *(const uint2*)&b1pk[((tau*NC1 + c)*32 + lane)*2];
                    mma8(acc[j], ah, bv);
                    mma8(acc[j], al, bv);
                }
            }
        }
        #pragma unroll
        for (int j = 0; j < NTW; j++) {
            const int tau = wid + 8*j;
            if (tau < NTAU) {
                const int u = 2*tau + uh;
                const float sA = (tq & 1) ? acc[j][0] : acc[j][2];
                const float sB = (tq & 1) ? acc[j][1] : acc[j][3];
                const float rA = __shfl_xor_sync(0xffffffffu, sA, 1);
                const float rB = __shfl_xor_sync(0xffffffffu, sB, 1);
                float gi, gf, gg, go;
                if (tq & 1) { gi = rA; gf = rB; gg = acc[j][2]; go = acc[j][3]; }
                else        { gi = acc[j][0]; gf = acc[j][1]; gg = rA; go = rB; }
                const float cn = fmaf(sigf(gf + bs1[j][1]), cst1[j],
                                      sigf(gi + bs1[j][0]) * ftanh(gg + bs1[j][2]));
                cst1[j] = cn;
                const float hn = sigf(go + bs1[j][3]) * ftanh(cn);
                if (u < Hh) {
                    const uint32_t hi = to_tf32(hn);
                    hbu[hidx(pw, 0, bmy, u)] = hi;
                    hbu[hidx(pw, 1, bmy, u)] = to_tf32(hn - __uint_as_float(hi));
                }
            }
        }
        if (tid < NB && tloc < 63 && t+1 < Lt) {
            const float xv = xch[tid*XCHP + tloc + 1];
            const uint32_t hi = to_tf32(xv);
            hbu[hidx(pw, 0, tid, 51)] = hi;
            hbu[hidx(pw, 1, tid, 51)] = to_tf32(xv - __uint_as_float(hi));
        }
        __syncthreads();   // new h1 (+x) visible

        // ================= Layer 2 =================
        #pragma unroll
        for (int j = 0; j < NTW; j++) { acc[j][0]=acc[j][1]=acc[j][2]=acc[j][3]=0.f; }
        #pragma unroll
        for (int c = 0; c < NC2; c++) {
            const int reg = (c < NC1) ? pw : qr;
            const int cc  = (c < NC1) ? c : c - NC1;
            const uint4 ah = *(const uint4*)&hbuf[reg*RSTRIDE + cc*128 + lane*4];
            const uint4 al = *(const uint4*)&hbuf[reg*RSTRIDE + NC1*128 + cc*128 + lane*4];
            #pragma unroll
            for (int j = 0; j < NTW; j++) {
                const int tau = wid + 8*j;
                if (tau < NTAU) {
                    const uint2 bv = *(const uint2*)&b2pk[((tau*NC2 + c)*32 + lane)*2];
                    mma8(acc[j], ah, bv);
                    mma8(acc[j], al, bv);
                }
            }
        }
        float ypart = 0.f;
        #pragma unroll
        for (int j = 0; j < NTW; j++) {
            const int tau = wid + 8*j;
            if (tau < NTAU) {
                const int u = 2*tau + uh;
                const float sA = (tq & 1) ? acc[j][0] : acc[j][2];
                const float sB = (tq & 1) ? acc[j][1] : acc[j][3];
                const float rA = __shfl_xor_sync(0xffffffffu, sA, 1);
                const float rB = __shfl_xor_sync(0xffffffffu, sB, 1);
                float gi, gf, gg, go;
                if (tq & 1) { gi = rA; gf = rB; gg = acc[j][2]; go = acc[j][3]; }
                else        { gi = acc[j][0]; gf = acc[j][1]; gg = rA; go = rB; }
                const float cn = fmaf(sigf(gf + bs2[j][1]), cst2[j],
                                      sigf(gi + bs2[j][0]) * ftanh(gg + bs2[j][2]));
                cst2[j] = cn;
                const float hn = sigf(go + bs2[j][3]) * ftanh(cn);
                if (u < Hh) {
                    const uint32_t hi = to_tf32(hn);
                    hbu[hidx(qw, 0, bmy, u)] = hi;
                    hbu[hidx(qw, 1, bmy, u)] = to_tf32(hn - __uint_as_float(hi));
                }
                ypart = fmaf(hn, wl[j], ypart);
            }
        }
        const float ys = ypart + __shfl_xor_sync(0xffffffffu, ypart, 2);
        if (tq < 2) opart[wid*NB + ((tq & 1) << 3) + gid] = ys;
        __syncthreads();   // h2 + opart visible

        if (tid < NB) {
            float s = sm[OFF_BLIN];
            #pragma unroll
            for (int w8 = 0; w8 < WARPS; w8++) s += opart[w8*NB + tid];
            och[tid*XCHP + tloc] = s;
        }

        // ---- flush output chunk (coalesced) ----
        if (tloc == 63 || t == Lt-1) {
            __syncthreads();
            const int wd = tloc + 1;
            for (int i = tid; i < NB*wd; i += THREADS) {
                const int row = i / wd, col = i - row*wd;
                out[(b0+row)*Lt + t0 + col] = och[row*XCHP + col];
            }
        }
    }
}

extern "C" void kernel_launch(void* const* d_in, const int* in_sizes, int n_in,
                              void* d_out, int out_size)
{
    const float* x     = (const float*)d_in[0];
    const float* wih1  = (const float*)d_in[1];
    const float* whh1  = (const float*)d_in[2];
    const float* bih1  = (const float*)d_in[3];
    const float* bhh1  = (const float*)d_in[4];
    const float* wih2  = (const float*)d_in[5];
    const float* whh2  = (const float*)d_in[6];
    const float* bih2  = (const float*)d_in[7];
    const float* bhh2  = (const float*)d_in[8];
    const float* wlin  = (const float*)d_in[9];
    const float* blin  = (const float*)d_in[10];
    float* out = (float*)d_out;

    const size_t smem = (size_t)SMEM_FLOATS * sizeof(float);
    cudaFuncSetAttribute(lstm_kernel, cudaFuncAttributeMaxDynamicSharedMemorySize, (int)smem);
    lstm_kernel<<<NCTA, THREADS, smem>>>(x, wih1, whh1, bih1, bhh1,
                                         wih2, whh2, bih2, bhh2,
                                         wlin, blin, out);
}

// round 8
// speedup vs baseline: 1.2121x; 1.2121x over previous
#include <cuda_runtime.h>
#include <cstdint>

#define Hh 51
#define Lt 999
#define NB 16
#define NCTA 128
#define THREADS 256
#define WARPS 8
#define NTW 4          // n8-tiles per warp (32 tiles, uniform)
#define NC1 7          // K-chunks layer1 (K=56: h1[51] + x + pad)
#define NC2 14         // K-chunks layer2 (K=112)
#define XCHP 65
#define RSTRIDE (2*NC1*128)   // per-region floats (hi+lo planes)

// shared memory float offsets
#define OFF_B1PK 0
#define SZ_B1PK (32*NC1*64)              // 14336
#define OFF_B2PK (OFF_B1PK + SZ_B1PK)
#define SZ_B2PK (32*NC2*64)              // 28672
#define OFF_HBUF (OFF_B2PK + SZ_B2PK)    // 4 regions: R0,R1 (h1+x), Q0,Q1 (h2)
#define SZ_HBUF (4*RSTRIDE)              // 7168
#define OFF_OCH  (OFF_HBUF + SZ_HBUF)
#define OFF_OP   (OFF_OCH + NB*XCHP)     // 2 x 128 double-buffered partials
#define OFF_BLIN (OFF_OP + 2*WARPS*NB)
#define SMEM_FLOATS (OFF_BLIN + 4)

__device__ __forceinline__ uint32_t to_tf32(float x) {
    uint32_t u; asm("cvt.rna.tf32.f32 %0, %1;" : "=r"(u) : "f"(x)); return u;
}
__device__ __forceinline__ void mma8(float* d, uint4 a, uint2 b) {
    asm("mma.sync.aligned.m16n8k8.row.col.f32.tf32.tf32.f32 "
        "{%0,%1,%2,%3}, {%4,%5,%6,%7}, {%8,%9}, {%0,%1,%2,%3};"
        : "+f"(d[0]), "+f"(d[1]), "+f"(d[2]), "+f"(d[3])
        : "r"(a.x), "r"(a.y), "r"(a.z), "r"(a.w), "r"(b.x), "r"(b.y));
}
__device__ __forceinline__ float frcp(float x) {
    float r; asm("rcp.approx.f32 %0, %1;" : "=f"(r) : "f"(x)); return r;
}
__device__ __forceinline__ float fex2(float x) {
    float r; asm("ex2.approx.f32 %0, %1;" : "=f"(r) : "f"(x)); return r;
}
__device__ __forceinline__ float sigf(float x) {
    return frcp(fex2(-1.4426950408889634f * x) + 1.0f);
}
__device__ __forceinline__ float ftanh(float x) {
    return fmaf(-2.0f, frcp(fex2(2.8853901817779268f * x) + 1.0f), 1.0f);
}
// hbuf slot for value (batch b, unit u), plane 0=hi 1=lo
__device__ __forceinline__ int hidx(int region, int plane, int b, int u) {
    const int colin = u & 7, ch = u >> 3;
    const int tl = ((b & 7) << 2) + (colin & 3);
    const int reg = ((colin >= 4) ? 2 : 0) + ((b >= 8) ? 1 : 0);
    return region*RSTRIDE + plane*(NC1*128) + ch*128 + tl*4 + reg;
}

__global__ void __launch_bounds__(THREADS, 1)
lstm_kernel(const float* __restrict__ x,
            const float* __restrict__ gWih1, const float* __restrict__ gWhh1,
            const float* __restrict__ gbih1, const float* __restrict__ gbhh1,
            const float* __restrict__ gWih2, const float* __restrict__ gWhh2,
            const float* __restrict__ gbih2, const float* __restrict__ gbhh2,
            const float* __restrict__ gWlin, const float* __restrict__ gblin,
            float* __restrict__ out)
{
    extern __shared__ float sm[];
    float* b1pk = sm + OFF_B1PK;
    float* b2pk = sm + OFF_B2PK;
    float* hbuf = sm + OFF_HBUF;
    uint32_t* hbu = (uint32_t*)hbuf;
    float* och  = sm + OFF_OCH;
    float* opart= sm + OFF_OP;

    const int tid  = threadIdx.x;
    const int wid  = tid >> 5;
    const int lane = tid & 31;
    const int gid  = lane >> 2, tq = lane & 3;
    const int bmy  = gid + ((tq & 1) << 3);   // this lane's batch
    const int uh   = tq >> 1;                 // unit half within tile
    const int b0   = blockIdx.x * NB;

    // ---- pack layer-1 weights (tf32, fragment order); bias column ZERO ----
    for (int idx = tid; idx < SZ_B1PK; idx += THREADS) {
        const int r   = idx & 1;
        const int ln  = (idx >> 1) & 31;
        const int c   = (idx >> 6) % NC1;
        const int tau = idx / (NC1 * 64);
        const int n = tau*8 + (ln >> 2);
        const int u = n >> 2, ty = n & 3;
        const int k = c*8 + (ln & 3) + 4*r;
        float v = 0.f;
        if (u < Hh) {
            const int R = ty*Hh + u;
            if (k < Hh)       v = gWhh1[R*Hh + k];
            else if (k == Hh) v = gWih1[R];          // x slot (unit 51)
        }
        b1pk[idx] = __uint_as_float(to_tf32(v));
    }
    // ---- pack layer-2 weights; x and bias columns ZERO ----
    for (int idx = tid; idx < SZ_B2PK; idx += THREADS) {
        const int r   = idx & 1;
        const int ln  = (idx >> 1) & 31;
        const int c   = (idx >> 6) % NC2;
        const int tau = idx / (NC2 * 64);
        const int n = tau*8 + (ln >> 2);
        const int u = n >> 2, ty = n & 3;
        const int k = c*8 + (ln & 3) + 4*r;
        float v = 0.f;
        if (u < Hh) {
            const int R = ty*Hh + u;
            if (k < Hh) v = gWih2[R*Hh + k];
            else if (k >= 56) { const int kq = k - 56; if (kq < Hh) v = gWhh2[R*Hh + kq]; }
        }
        b2pk[idx] = __uint_as_float(to_tf32(v));
    }
    for (int i = tid; i < SZ_HBUF; i += THREADS) hbuf[i] = 0.f;
    if (tid == 0) sm[OFF_BLIN] = gblin[0];
    __syncthreads();
    // x[0] into region 1 (prologue read region)
    if (tid < NB) {
        const float xv = x[(b0 + tid)*Lt + 0];
        const uint32_t hi = to_tf32(xv);
        hbu[hidx(1, 0, tid, 51)] = hi;
        hbu[hidx(1, 1, tid, 51)] = to_tf32(xv - __uint_as_float(hi));
    }
    // per-lane exact bias + W_lin
    float wl[NTW], bs1[NTW][4], bs2[NTW][4];
    #pragma unroll
    for (int j = 0; j < NTW; j++) {
        const int u = 2*(wid + 8*j) + uh;
        wl[j] = (u < Hh) ? gWlin[u] : 0.f;
        #pragma unroll
        for (int ty = 0; ty < 4; ty++) {
            const int R = ty*Hh + u;
            bs1[j][ty] = (u < Hh) ? (gbih1[R] + gbhh1[R]) : 0.f;
            bs2[j][ty] = (u < Hh) ? (gbih2[R] + gbhh2[R]) : 0.f;
        }
    }
    float cst1[NTW] = {0.f,0.f,0.f,0.f}, cst2[NTW] = {0.f,0.f,0.f,0.f};
    __syncthreads();

    // ================= prologue: h1[0] = cell1(x[0], 0) =================
    {
        float xf = 0.f;
        if (tid < NB) xf = x[(b0 + tid)*Lt + 1];   // prefetch x[1] (Lt>1)
        float a1[NTW][4];
        #pragma unroll
        for (int j = 0; j < NTW; j++) { a1[j][0]=a1[j][1]=a1[j][2]=a1[j][3]=0.f; }
        #pragma unroll
        for (int c = 0; c < NC1; c++) {
            const uint4 ah = *(const uint4*)&hbuf[1*RSTRIDE + c*128 + lane*4];
            const uint4 al = *(const uint4*)&hbuf[1*RSTRIDE + NC1*128 + c*128 + lane*4];
            #pragma unroll
            for (int j = 0; j < NTW; j++) {
                const int tau = wid + 8*j;
                const uint2 bv = *(const uint2*)&b1pk[((tau*NC1 + c)*32 + lane)*2];
                mma8(a1[j], ah, bv);
                mma8(a1[j], al, bv);
            }
        }
        #pragma unroll
        for (int j = 0; j < NTW; j++) {
            const int u = 2*(wid + 8*j) + uh;
            const float sA = (tq & 1) ? a1[j][0] : a1[j][2];
            const float sB = (tq & 1) ? a1[j][1] : a1[j][3];
            const float rA = __shfl_xor_sync(0xffffffffu, sA, 1);
            const float rB = __shfl_xor_sync(0xffffffffu, sB, 1);
            float gi, gf, gg, go;
            if (tq & 1) { gi = rA; gf = rB; gg = a1[j][2]; go = a1[j][3]; }
            else        { gi = a1[j][0]; gf = a1[j][1]; gg = rA; go = rB; }
            const float cn = fmaf(sigf(gf + bs1[j][1]), cst1[j],
                                  sigf(gi + bs1[j][0]) * ftanh(gg + bs1[j][2]));
            cst1[j] = cn;
            const float hn = sigf(go + bs1[j][3]) * ftanh(cn);
            if (u < Hh) {
                const uint32_t hi = to_tf32(hn);
                hbu[hidx(0, 0, bmy, u)] = hi;
                hbu[hidx(0, 1, bmy, u)] = to_tf32(hn - __uint_as_float(hi));
            }
        }
        if (tid < NB) {
            const uint32_t hi = to_tf32(xf);
            hbu[hidx(0, 0, tid, 51)] = hi;
            hbu[hidx(0, 1, tid, 51)] = to_tf32(xf - __uint_as_float(hi));
        }
        __syncthreads();
    }

    // ================= main loop: step n does L1[n+1] + L2[n] =================
    for (int n = 0; n < Lt; ++n) {
        const int rr = n & 1, wr = 1 - rr;       // R (h1+x) regions
        const int qr = 2 + rr, qw = 3 - rr;      // Q (h2) regions

        float xf = 0.f;
        const bool havex = (tid < NB) && (n + 2 < Lt);
        if (havex) xf = x[(b0 + tid)*Lt + n + 2];   // prefetch (hidden by MMA phase)

        float a1[NTW][4], a2[NTW][4];
        #pragma unroll
        for (int j = 0; j < NTW; j++) {
            a1[j][0]=a1[j][1]=a1[j][2]=a1[j][3]=0.f;
            a2[j][0]=a2[j][1]=a2[j][2]=a2[j][3]=0.f;
        }
        // h1[n] (+x[n+1]) chunks feed BOTH layer-1 and layer-2 MMAs
        #pragma unroll
        for (int c = 0; c < NC1; c++) {
            const uint4 ah = *(const uint4*)&hbuf[rr*RSTRIDE + c*128 + lane*4];
            const uint4 al = *(const uint4*)&hbuf[rr*RSTRIDE + NC1*128 + c*128 + lane*4];
            #pragma unroll
            for (int j = 0; j < NTW; j++) {
                const int tau = wid + 8*j;
                const uint2 b1v = *(const uint2*)&b1pk[((tau*NC1 + c)*32 + lane)*2];
                mma8(a1[j], ah, b1v);
                mma8(a1[j], al, b1v);
                const uint2 b2v = *(const uint2*)&b2pk[((tau*NC2 + c)*32 + lane)*2];
                mma8(a2[j], ah, b2v);
                mma8(a2[j], al, b2v);
            }
        }
        // h2[n-1] chunks feed layer-2 only
        #pragma unroll
        for (int c = NC1; c < NC2; c++) {
            const int cc = c - NC1;
            const uint4 ah = *(const uint4*)&hbuf[qr*RSTRIDE + cc*128 + lane*4];
            const uint4 al = *(const uint4*)&hbuf[qr*RSTRIDE + NC1*128 + cc*128 + lane*4];
            #pragma unroll
            for (int j = 0; j < NTW; j++) {
                const int tau = wid + 8*j;
                const uint2 b2v = *(const uint2*)&b2pk[((tau*NC2 + c)*32 + lane)*2];
                mma8(a2[j], ah, b2v);
                mma8(a2[j], al, b2v);
            }
        }

        // ---- epilogue: L1 -> h1[n+1] into wr ----
        #pragma unroll
        for (int j = 0; j < NTW; j++) {
            const int u = 2*(wid + 8*j) + uh;
            const float sA = (tq & 1) ? a1[j][0] : a1[j][2];
            const float sB = (tq & 1) ? a1[j][1] : a1[j][3];
            const float rA = __shfl_xor_sync(0xffffffffu, sA, 1);
            const float rB = __shfl_xor_sync(0xffffffffu, sB, 1);
            float gi, gf, gg, go;
            if (tq & 1) { gi = rA; gf = rB; gg = a1[j][2]; go = a1[j][3]; }
            else        { gi = a1[j][0]; gf = a1[j][1]; gg = rA; go = rB; }
            const float cn = fmaf(sigf(gf + bs1[j][1]), cst1[j],
                                  sigf(gi + bs1[j][0]) * ftanh(gg + bs1[j][2]));
            cst1[j] = cn;
            const float hn = sigf(go + bs1[j][3]) * ftanh(cn);
            if (u < Hh) {
                const uint32_t hi = to_tf32(hn);
                hbu[hidx(wr, 0, bmy, u)] = hi;
                hbu[hidx(wr, 1, bmy, u)] = to_tf32(hn - __uint_as_float(hi));
            }
        }
        // ---- epilogue: L2 -> h2[n] into qw, output partial ----
        float ypart = 0.f;
        #pragma unroll
        for (int j = 0; j < NTW; j++) {
            const int u = 2*(wid + 8*j) + uh;
            const float sA = (tq & 1) ? a2[j][0] : a2[j][2];
            const float sB = (tq & 1) ? a2[j][1] : a2[j][3];
            const float rA = __shfl_xor_sync(0xffffffffu, sA, 1);
            const float rB = __shfl_xor_sync(0xffffffffu, sB, 1);
            float gi, gf, gg, go;
            if (tq & 1) { gi = rA; gf = rB; gg = a2[j][2]; go = a2[j][3]; }
            else        { gi = a2[j][0]; gf = a2[j][1]; gg = rA; go = rB; }
            const float cn = fmaf(sigf(gf + bs2[j][1]), cst2[j],
                                  sigf(gi + bs2[j][0]) * ftanh(gg + bs2[j][2]));
            cst2[j] = cn;
            const float hn = sigf(go + bs2[j][3]) * ftanh(cn);
            if (u < Hh) {
                const uint32_t hi = to_tf32(hn);
                hbu[hidx(qw, 0, bmy, u)] = hi;
                hbu[hidx(qw, 1, bmy, u)] = to_tf32(hn - __uint_as_float(hi));
            }
            ypart = fmaf(hn, wl[j], ypart);
        }
        if (havex) {
            const uint32_t hi = to_tf32(xf);
            hbu[hidx(wr, 0, tid, 51)] = hi;
            hbu[hidx(wr, 1, tid, 51)] = to_tf32(xf - __uint_as_float(hi));
        }
        const float ys = ypart + __shfl_xor_sync(0xffffffffu, ypart, 2);
        if (tq < 2) opart[(n & 1)*(WARPS*NB) + wid*NB + ((tq & 1) << 3) + gid] = ys;
        __syncthreads();   // THE one barrier per step

        if (tid < NB) {
            float s = sm[OFF_BLIN];
            #pragma unroll
            for (int w8 = 0; w8 < WARPS; w8++)
                s += opart[(n & 1)*(WARPS*NB) + w8*NB + tid];
            och[tid*XCHP + (n & 63)] = s;
        }

        // ---- flush output chunk (coalesced) ----
        if ((n & 63) == 63 || n == Lt-1) {
            __syncthreads();
            const int t0c = n & ~63;
            const int wd = (n & 63) + 1;
            for (int i = tid; i < NB*wd; i += THREADS) {
                const int row = i / wd, col = i - row*wd;
                out[(b0+row)*Lt + t0c + col] = och[row*XCHP + col];
            }
        }
    }
}

extern "C" void kernel_launch(void* const* d_in, const int* in_sizes, int n_in,
                              void* d_out, int out_size)
{
    const float* x     = (const float*)d_in[0];
    const float* wih1  = (const float*)d_in[1];
    const float* whh1  = (const float*)d_in[2];
    const float* bih1  = (const float*)d_in[3];
    const float* bhh1  = (const float*)d_in[4];
    const float* wih2  = (const float*)d_in[5];
    const float* whh2  = (const float*)d_in[6];
    const float* bih2  = (const float*)d_in[7];
    const float* bhh2  = (const float*)d_in[8];
    const float* wlin  = (const float*)d_in[9];
    const float* blin  = (const float*)d_in[10];
    float* out = (float*)d_out;

    const size_t smem = (size_t)SMEM_FLOATS * sizeof(float);
    cudaFuncSetAttribute(lstm_kernel, cudaFuncAttributeMaxDynamicSharedMemorySize, (int)smem);
    lstm_kernel<<<NCTA, THREADS, smem>>>(x, wih1, whh1, bih1, bhh1,
                                         wih2, whh2, bih2, bhh2,
                                         wlin, blin, out);
}